// round 1
// baseline (speedup 1.0000x reference)
#include <cuda_runtime.h>
#include <math.h>

#define NB    4096
#define NROWS 8192
#define DDIM  128
#define BM    128
#define BN    256

// Scratch (static device memory -- no allocations allowed)
__device__ float g_reps[NROWS * DDIM];
__device__ float g_rowsum[NROWS];
__device__ float g_pos[NROWS];
__device__ float g_self[NROWS];

// ---------- packed f32x2 helpers (Blackwell FFMA2 path) ----------
__device__ __forceinline__ unsigned long long pk2(float x, float y) {
    unsigned long long r;
    asm("mov.b64 %0, {%1, %2};" : "=l"(r) : "f"(x), "f"(y));
    return r;
}
__device__ __forceinline__ void fma2(unsigned long long &d, unsigned long long a, unsigned long long b) {
    asm("fma.rn.f32x2 %0, %1, %2, %0;" : "+l"(d) : "l"(a), "l"(b));
}
__device__ __forceinline__ float2 upk2(unsigned long long r) {
    float2 v;
    asm("mov.b64 {%0, %1}, %2;" : "=f"(v.x), "=f"(v.y) : "l"(r));
    return v;
}

// ---------- K1: L2-normalize rows, zero row accumulators ----------
__global__ void __launch_bounds__(256) k_norm(const float* __restrict__ p1,
                                              const float* __restrict__ p2) {
    int gw   = (blockIdx.x * blockDim.x + threadIdx.x) >> 5;   // one warp per row
    int lane = threadIdx.x & 31;
    if (gw >= NROWS) return;
    const float* src = (gw < NB) ? (p1 + (size_t)gw * DDIM)
                                 : (p2 + (size_t)(gw - NB) * DDIM);
    float4 v = *(const float4*)(src + lane * 4);
    float ss = v.x * v.x + v.y * v.y + v.z * v.z + v.w * v.w;
#pragma unroll
    for (int o = 16; o; o >>= 1) ss += __shfl_xor_sync(0xffffffffu, ss, o);
    float inv = 1.0f / fmaxf(sqrtf(ss), 1e-12f);
    v.x *= inv; v.y *= inv; v.z *= inv; v.w *= inv;
    *(float4*)(g_reps + (size_t)gw * DDIM + lane * 4) = v;
    if (lane == 0) g_rowsum[gw] = 0.0f;
}

// ---------- K2: fused sim-GEMM + exp + row-sum ----------
// smem: As [128k][128 rows] + Bs [128k][256 cols], k-major, XOR swizzled
extern __shared__ float smem_f[];

__global__ void __launch_bounds__(256) k_gemm() {
    float* As = smem_f;                 // DDIM * BM floats
    float* Bs = smem_f + DDIM * BM;     // DDIM * BN floats
    const int tid = threadIdx.x;
    const int r0 = blockIdx.y * BM;
    const int c0 = blockIdx.x * BN;

    // Load + transpose A panel (rows r0..r0+127)
#pragma unroll
    for (int it = 0; it < (BM * DDIM / 4) / 256; ++it) {      // 16 iters
        int idx = tid + it * 256;
        int row = idx >> 5;            // 32 float4 per row
        int kq  = idx & 31;            // float4 index along k
        float4 v = *(const float4*)(g_reps + (size_t)(r0 + row) * DDIM + kq * 4);
        int g = row >> 2, e = row & 3;
        int p = (((g ^ (kq & 7)) << 2) + e);
        As[(kq * 4 + 0) * BM + p] = v.x;
        As[(kq * 4 + 1) * BM + p] = v.y;
        As[(kq * 4 + 2) * BM + p] = v.z;
        As[(kq * 4 + 3) * BM + p] = v.w;
    }
    // Load + transpose B panel (cols = rows c0..c0+255)
#pragma unroll
    for (int it = 0; it < (BN * DDIM / 4) / 256; ++it) {      // 32 iters
        int idx = tid + it * 256;
        int row = idx >> 5;
        int kq  = idx & 31;
        float4 v = *(const float4*)(g_reps + (size_t)(c0 + row) * DDIM + kq * 4);
        int g = row >> 2, e = row & 3;
        int p = (((g ^ (kq & 7)) << 2) + e);
        Bs[(kq * 4 + 0) * BN + p] = v.x;
        Bs[(kq * 4 + 1) * BN + p] = v.y;
        Bs[(kq * 4 + 2) * BN + p] = v.z;
        Bs[(kq * 4 + 3) * BN + p] = v.w;
    }
    __syncthreads();

    const int ty = tid >> 4;   // 0..15 -> rows ty*8..ty*8+7
    const int tx = tid & 15;   // 0..15 -> cols {4*(tx+16q)+e}

    unsigned long long acc[8][8];
#pragma unroll
    for (int i = 0; i < 8; ++i)
#pragma unroll
        for (int j = 0; j < 8; ++j) acc[i][j] = 0ULL;

#pragma unroll 4
    for (int k = 0; k < DDIM; ++k) {
        const int z = (k >> 2) & 7;
        const float4* Ak = (const float4*)(As + k * BM);
        float4 a0 = Ak[(2 * ty) ^ z];
        float4 a1 = Ak[(2 * ty + 1) ^ z];
        unsigned long long a2[8];
        a2[0] = pk2(a0.x, a0.x); a2[1] = pk2(a0.y, a0.y);
        a2[2] = pk2(a0.z, a0.z); a2[3] = pk2(a0.w, a0.w);
        a2[4] = pk2(a1.x, a1.x); a2[5] = pk2(a1.y, a1.y);
        a2[6] = pk2(a1.z, a1.z); a2[7] = pk2(a1.w, a1.w);

        const float4* Bk = (const float4*)(Bs + k * BN);
        const int bx = tx ^ z;
        float4 b0 = Bk[bx];
        float4 b1 = Bk[bx + 16];
        float4 b2 = Bk[bx + 32];
        float4 b3 = Bk[bx + 48];
        unsigned long long bb[8];
        bb[0] = pk2(b0.x, b0.y); bb[1] = pk2(b0.z, b0.w);
        bb[2] = pk2(b1.x, b1.y); bb[3] = pk2(b1.z, b1.w);
        bb[4] = pk2(b2.x, b2.y); bb[5] = pk2(b2.z, b2.w);
        bb[6] = pk2(b3.x, b3.y); bb[7] = pk2(b3.z, b3.w);

#pragma unroll
        for (int i = 0; i < 8; ++i)
#pragma unroll
            for (int j = 0; j < 8; ++j)
                fma2(acc[i][j], a2[i], bb[j]);
    }

    // Epilogue: exp(sim/T) with T=0.5, per-row partial sums, warp-reduce over tx
#pragma unroll
    for (int i = 0; i < 8; ++i) {
        float s = 0.0f;
#pragma unroll
        for (int j = 0; j < 8; ++j) {
            float2 v = upk2(acc[i][j]);
            s += __expf(2.0f * v.x) + __expf(2.0f * v.y);
        }
#pragma unroll
        for (int o = 8; o; o >>= 1) s += __shfl_down_sync(0xffffffffu, s, o);
        if (tx == 0) atomicAdd(&g_rowsum[r0 + ty * 8 + i], s);
    }
}

// ---------- K3: positives + self-similarity ----------
__global__ void __launch_bounds__(256) k_pos() {
    int gw   = (blockIdx.x * blockDim.x + threadIdx.x) >> 5;
    int lane = threadIdx.x & 31;
    if (gw >= NROWS) return;
    int pr = gw ^ NB;   // partner row: +B for r<B, -B otherwise
    float4 a = *(const float4*)(g_reps + (size_t)gw * DDIM + lane * 4);
    float4 b = *(const float4*)(g_reps + (size_t)pr * DDIM + lane * 4);
    float pos  = a.x * b.x + a.y * b.y + a.z * b.z + a.w * b.w;
    float self = a.x * a.x + a.y * a.y + a.z * a.z + a.w * a.w;
#pragma unroll
    for (int o = 16; o; o >>= 1) {
        pos  += __shfl_xor_sync(0xffffffffu, pos, o);
        self += __shfl_xor_sync(0xffffffffu, self, o);
    }
    if (lane == 0) { g_pos[gw] = pos; g_self[gw] = self; }
}

// ---------- K4: final loss reduction ----------
__global__ void __launch_bounds__(256) k_final(float* __restrict__ out) {
    __shared__ float red[256];
    int tid = threadIdx.x;
    float local = 0.0f;
    for (int r = tid; r < NROWS; r += 256) {
        float den = g_rowsum[r] - __expf(2.0f * g_self[r]);  // drop diagonal term
        local += logf(den) - 2.0f * g_pos[r];                // log(den) - pos/T
    }
    red[tid] = local;
    __syncthreads();
#pragma unroll
    for (int o = 128; o; o >>= 1) {
        if (tid < o) red[tid] += red[tid + o];
        __syncthreads();
    }
    if (tid == 0) out[0] = red[0] / (float)NROWS;
}

// ---------- launcher ----------
extern "C" void kernel_launch(void* const* d_in, const int* in_sizes, int n_in,
                              void* d_out, int out_size) {
    const float* p1 = (const float*)d_in[0];
    const float* p2 = (const float*)d_in[1];
    float* out = (float*)d_out;

    size_t smem = (size_t)(DDIM * BM + DDIM * BN) * sizeof(float);  // 192 KB
    cudaFuncSetAttribute(k_gemm, cudaFuncAttributeMaxDynamicSharedMemorySize, (int)smem);

    k_norm<<<NROWS / 8, 256>>>(p1, p2);
    dim3 grid(NROWS / BN, NROWS / BM);   // (32, 64) = 2048 blocks
    k_gemm<<<grid, 256, smem>>>();
    k_pos<<<NROWS / 8, 256>>>();
    k_final<<<1, 256>>>(out);
}

// round 3
// speedup vs baseline: 2.4754x; 2.4754x over previous
#include <cuda_runtime.h>
#include <cuda_bf16.h>
#include <math.h>
#include <stdint.h>

#define NB     4096
#define NROWS  8192
#define DDIM   128

// ---------------- static scratch (no allocations allowed) ----------------
__device__ float         g_reps[NROWS * DDIM];
__device__ __nv_bfloat16 g_hi[NROWS * DDIM];
__device__ __nv_bfloat16 g_lo[NROWS * DDIM];
__device__ float         g_rowsum[NROWS];
__device__ float         g_pos[NROWS];
__device__ float         g_self[NROWS];

// ---------------- helpers ----------------
__device__ __forceinline__ uint32_t smem_u32(const void* p) {
    uint32_t a;
    asm("{ .reg .u64 t; cvta.to.shared.u64 t, %1; cvt.u32.u64 %0, t; }"
        : "=r"(a) : "l"(p));
    return a;
}
__device__ __forceinline__ void ldsm4(uint32_t* r, uint32_t addr) {
    asm volatile("ldmatrix.sync.aligned.m8n8.x4.shared.b16 {%0,%1,%2,%3}, [%4];"
                 : "=r"(r[0]), "=r"(r[1]), "=r"(r[2]), "=r"(r[3]) : "r"(addr));
}
__device__ __forceinline__ void mma16816(float* d, const uint32_t* a,
                                         uint32_t b0, uint32_t b1) {
    asm volatile("mma.sync.aligned.m16n8k16.row.col.f32.bf16.bf16.f32 "
                 "{%0,%1,%2,%3}, {%4,%5,%6,%7}, {%8,%9}, {%0,%1,%2,%3};"
                 : "+f"(d[0]), "+f"(d[1]), "+f"(d[2]), "+f"(d[3])
                 : "r"(a[0]), "r"(a[1]), "r"(a[2]), "r"(a[3]), "r"(b0), "r"(b1));
}

// smem tile layout: 128 rows, pitch 272 B (136 bf16). 17 quad-banks per row
// -> ldmatrix phases conflict-free. Three tiles: A_hi, A_lo, B_hi + row partials.
#define PITCH    272
#define SM_AHI   0
#define SM_ALO   (128 * PITCH)
#define SM_B     (2 * 128 * PITCH)
#define SM_ROWS  (3 * 128 * PITCH)
#define SMEM_SZ  (SM_ROWS + 128 * 4)

// ---------------- K1: normalize + bf16 hi/lo split ----------------
__global__ void __launch_bounds__(256) k_norm(const float* __restrict__ p1,
                                              const float* __restrict__ p2) {
    int gw = (blockIdx.x * blockDim.x + threadIdx.x) >> 5;
    int lane = threadIdx.x & 31;
    if (gw >= NROWS) return;
    const float* src = (gw < NB) ? (p1 + (size_t)gw * DDIM)
                                 : (p2 + (size_t)(gw - NB) * DDIM);
    float4 v = *(const float4*)(src + lane * 4);
    float ss = v.x * v.x + v.y * v.y + v.z * v.z + v.w * v.w;
#pragma unroll
    for (int o = 16; o; o >>= 1) ss += __shfl_xor_sync(0xffffffffu, ss, o);
    float inv = 1.0f / fmaxf(sqrtf(ss), 1e-12f);
    v.x *= inv; v.y *= inv; v.z *= inv; v.w *= inv;
    size_t base = (size_t)gw * DDIM + lane * 4;
    *(float4*)(g_reps + base) = v;
    __nv_bfloat16 hx = __float2bfloat16(v.x), hy = __float2bfloat16(v.y);
    __nv_bfloat16 hz = __float2bfloat16(v.z), hw = __float2bfloat16(v.w);
    __nv_bfloat16 lx = __float2bfloat16(v.x - __bfloat162float(hx));
    __nv_bfloat16 ly = __float2bfloat16(v.y - __bfloat162float(hy));
    __nv_bfloat16 lz = __float2bfloat16(v.z - __bfloat162float(hz));
    __nv_bfloat16 lw = __float2bfloat16(v.w - __bfloat162float(hw));
    __nv_bfloat162 h01; h01.x = hx; h01.y = hy;
    __nv_bfloat162 h23; h23.x = hz; h23.y = hw;
    __nv_bfloat162 l01; l01.x = lx; l01.y = ly;
    __nv_bfloat162 l23; l23.x = lz; l23.y = lw;
    *(__nv_bfloat162*)(g_hi + base)     = h01;
    *(__nv_bfloat162*)(g_hi + base + 2) = h23;
    *(__nv_bfloat162*)(g_lo + base)     = l01;
    *(__nv_bfloat162*)(g_lo + base + 2) = l23;
    if (lane == 0) g_rowsum[gw] = 0.0f;
}

// ---------------- K2: HMMA sim-GEMM + exp + row-sum ----------------
extern __shared__ char smem_raw[];

__global__ void __launch_bounds__(256, 2) k_gemm() {
    const int tid  = threadIdx.x;
    const int wid  = tid >> 5;
    const int lane = tid & 31;
    const int r0 = blockIdx.y * 128;
    const int c0 = blockIdx.x * 128;

    float* smrows = (float*)(smem_raw + SM_ROWS);
    if (tid < 128) smrows[tid] = 0.0f;

    // load A_hi / A_lo (rows r0..+127) and B_hi (rows c0..+127), coalesced
#pragma unroll
    for (int it = 0; it < 8; ++it) {
        int idx = tid + it * 256;
        int row = idx >> 4;
        int seg = idx & 15;
        uint32_t so = (uint32_t)(row * PITCH + seg * 16);
        *(uint4*)(smem_raw + SM_AHI + so) =
            *(const uint4*)(g_hi + (size_t)(r0 + row) * DDIM + seg * 8);
        *(uint4*)(smem_raw + SM_ALO + so) =
            *(const uint4*)(g_lo + (size_t)(r0 + row) * DDIM + seg * 8);
        *(uint4*)(smem_raw + SM_B + so) =
            *(const uint4*)(g_hi + (size_t)(c0 + row) * DDIM + seg * 8);
    }
    __syncthreads();

    const uint32_t sb = smem_u32(smem_raw);
    const int wm = wid >> 2;          // 0..1 -> rows 64*wm
    const int wn = wid & 3;           // 0..3 -> cols 32*wn

    // ldmatrix base addresses
    const uint32_t a_base = sb +
        (uint32_t)((64 * wm + (lane & 15)) * PITCH + (lane >> 4) * 16);
    const int brow = 32 * wn + (lane & 7) + ((lane >> 4) << 3);
    const uint32_t b_base = sb + SM_B +
        (uint32_t)(brow * PITCH + ((lane >> 3) & 1) * 16);

    float acc[4][4][4];
#pragma unroll
    for (int mi = 0; mi < 4; ++mi)
#pragma unroll
        for (int nj = 0; nj < 4; ++nj)
#pragma unroll
            for (int e = 0; e < 4; ++e) acc[mi][nj][e] = 0.0f;

#pragma unroll
    for (int kk = 0; kk < 8; ++kk) {
        uint32_t b[2][4];
        ldsm4(b[0], b_base + kk * 32);                 // n-octets 0,1 (cols 0..15)
        ldsm4(b[1], b_base + 16 * PITCH + kk * 32);    // n-octets 2,3 (cols 16..31)
#pragma unroll
        for (int g = 0; g < 2; ++g) {
            uint32_t ab = a_base + (g ? SM_ALO : SM_AHI) + kk * 32;
#pragma unroll
            for (int mi = 0; mi < 4; ++mi) {
                uint32_t a[4];
                ldsm4(a, ab + mi * 16 * PITCH);
                mma16816(acc[mi][0], a, b[0][0], b[0][1]);
                mma16816(acc[mi][1], a, b[0][2], b[0][3]);
                mma16816(acc[mi][2], a, b[1][0], b[1][1]);
                mma16816(acc[mi][3], a, b[1][2], b[1][3]);
            }
        }
    }

    // epilogue: exp(2*sim), per-row partial sums into smem
    const int rbase = 64 * wm + (lane >> 2);
#pragma unroll
    for (int mi = 0; mi < 4; ++mi) {
        float slo = 0.0f, shi = 0.0f;
#pragma unroll
        for (int nj = 0; nj < 4; ++nj) {
            slo += __expf(2.0f * acc[mi][nj][0]) + __expf(2.0f * acc[mi][nj][1]);
            shi += __expf(2.0f * acc[mi][nj][2]) + __expf(2.0f * acc[mi][nj][3]);
        }
        atomicAdd(&smrows[rbase + 16 * mi],     slo);
        atomicAdd(&smrows[rbase + 16 * mi + 8], shi);
    }
    __syncthreads();
    if (tid < 128) atomicAdd(&g_rowsum[r0 + tid], smrows[tid]);
}

// ---------------- K3: positives + self (exact fp32) ----------------
__global__ void __launch_bounds__(256) k_pos() {
    int gw = (blockIdx.x * blockDim.x + threadIdx.x) >> 5;
    int lane = threadIdx.x & 31;
    if (gw >= NROWS) return;
    int pr = gw ^ NB;
    float4 a = *(const float4*)(g_reps + (size_t)gw * DDIM + lane * 4);
    float4 b = *(const float4*)(g_reps + (size_t)pr * DDIM + lane * 4);
    float pos  = a.x * b.x + a.y * b.y + a.z * b.z + a.w * b.w;
    float self = a.x * a.x + a.y * a.y + a.z * a.z + a.w * a.w;
#pragma unroll
    for (int o = 16; o; o >>= 1) {
        pos  += __shfl_xor_sync(0xffffffffu, pos, o);
        self += __shfl_xor_sync(0xffffffffu, self, o);
    }
    if (lane == 0) { g_pos[gw] = pos; g_self[gw] = self; }
}

// ---------------- K4: final reduction ----------------
// NOTE: the GEMM's diagonal entry is the bf16 self-sim; we subtract the exact
// fp32 self term instead -- the mismatch is O(1e-6) of an 8.5e3 denominator.
__global__ void __launch_bounds__(256) k_final(float* __restrict__ out) {
    __shared__ float red[256];
    int tid = threadIdx.x;
    float local = 0.0f;
    for (int r = tid; r < NROWS; r += 256) {
        float den = g_rowsum[r] - __expf(2.0f * g_self[r]);
        local += logf(den) - 2.0f * g_pos[r];
    }
    red[tid] = local;
    __syncthreads();
#pragma unroll
    for (int o = 128; o; o >>= 1) {
        if (tid < o) red[tid] += red[tid + o];
        __syncthreads();
    }
    if (tid == 0) out[0] = red[0] / (float)NROWS;
}

// ---------------- launcher ----------------
extern "C" void kernel_launch(void* const* d_in, const int* in_sizes, int n_in,
                              void* d_out, int out_size) {
    const float* p1 = (const float*)d_in[0];
    const float* p2 = (const float*)d_in[1];
    float* out = (float*)d_out;

    cudaFuncSetAttribute(k_gemm, cudaFuncAttributeMaxDynamicSharedMemorySize, SMEM_SZ);

    k_norm<<<NROWS / 8, 256>>>(p1, p2);
    dim3 grid(NROWS / 128, NROWS / 128);   // 64 x 64 CTAs
    k_gemm<<<grid, 256, SMEM_SZ>>>();
    k_pos<<<NROWS / 8, 256>>>();
    k_final<<<1, 256>>>(out);
}

// round 4
// speedup vs baseline: 3.9248x; 1.5855x over previous
#include <cuda_runtime.h>
#include <cuda_bf16.h>
#include <math.h>
#include <stdint.h>

#define NB     4096
#define NROWS  8192
#define DDIM   128
#define NTILE  64          // 8192 / 128
#define NCTA   2080        // NTILE*(NTILE+1)/2 upper-triangle tiles

// ---------------- static scratch (no allocations allowed) ----------------
__device__ float         g_reps[NROWS * DDIM];
__device__ __nv_bfloat16 g_hi[NROWS * DDIM];
__device__ __nv_bfloat16 g_lo[NROWS * DDIM];
__device__ float         g_rowsum[NROWS];
__device__ float         g_pos[NROWS];
__device__ float         g_self[NROWS];

// ---------------- helpers ----------------
__device__ __forceinline__ uint32_t smem_u32(const void* p) {
    uint32_t a;
    asm("{ .reg .u64 t; cvta.to.shared.u64 t, %1; cvt.u32.u64 %0, t; }"
        : "=r"(a) : "l"(p));
    return a;
}
__device__ __forceinline__ void ldsm4(uint32_t* r, uint32_t addr) {
    asm volatile("ldmatrix.sync.aligned.m8n8.x4.shared.b16 {%0,%1,%2,%3}, [%4];"
                 : "=r"(r[0]), "=r"(r[1]), "=r"(r[2]), "=r"(r[3]) : "r"(addr));
}
__device__ __forceinline__ void mma16816(float* d, const uint32_t* a,
                                         uint32_t b0, uint32_t b1) {
    asm volatile("mma.sync.aligned.m16n8k16.row.col.f32.bf16.bf16.f32 "
                 "{%0,%1,%2,%3}, {%4,%5,%6,%7}, {%8,%9}, {%0,%1,%2,%3};"
                 : "+f"(d[0]), "+f"(d[1]), "+f"(d[2]), "+f"(d[3])
                 : "r"(a[0]), "r"(a[1]), "r"(a[2]), "r"(a[3]), "r"(b0), "r"(b1));
}

// smem tile layout: 128 rows, pitch 272 B (17x16B -> conflict-free ldmatrix)
#define PITCH    272
#define SM_AHI   0
#define SM_ALO   (128 * PITCH)
#define SM_B     (2 * 128 * PITCH)
#define SM_ROWS  (3 * 128 * PITCH)
#define SM_COLS  (SM_ROWS + 128 * 4)
#define SMEM_SZ  (SM_COLS + 128 * 4)

// ---------------- K1: normalize pair + bf16 split + positives/self ----------------
__global__ void __launch_bounds__(256) k_norm(const float* __restrict__ p1,
                                              const float* __restrict__ p2) {
    int gw = (blockIdx.x * blockDim.x + threadIdx.x) >> 5;   // pair index 0..NB-1
    int lane = threadIdx.x & 31;
    if (gw >= NB) return;
    float4 v1 = *(const float4*)(p1 + (size_t)gw * DDIM + lane * 4);
    float4 v2 = *(const float4*)(p2 + (size_t)gw * DDIM + lane * 4);
    float ss1 = v1.x * v1.x + v1.y * v1.y + v1.z * v1.z + v1.w * v1.w;
    float ss2 = v2.x * v2.x + v2.y * v2.y + v2.z * v2.z + v2.w * v2.w;
    float cx  = v1.x * v2.x + v1.y * v2.y + v1.z * v2.z + v1.w * v2.w;
#pragma unroll
    for (int o = 16; o; o >>= 1) {
        ss1 += __shfl_xor_sync(0xffffffffu, ss1, o);
        ss2 += __shfl_xor_sync(0xffffffffu, ss2, o);
        cx  += __shfl_xor_sync(0xffffffffu, cx,  o);
    }
    float inv1 = 1.0f / fmaxf(sqrtf(ss1), 1e-12f);
    float inv2 = 1.0f / fmaxf(sqrtf(ss2), 1e-12f);

    size_t b1 = (size_t)gw * DDIM + lane * 4;
    size_t b2 = (size_t)(gw + NB) * DDIM + lane * 4;
#pragma unroll
    for (int half = 0; half < 2; ++half) {
        float4 v = half ? v2 : v1;
        float inv = half ? inv2 : inv1;
        size_t base = half ? b2 : b1;
        v.x *= inv; v.y *= inv; v.z *= inv; v.w *= inv;
        *(float4*)(g_reps + base) = v;
        __nv_bfloat16 hx = __float2bfloat16(v.x), hy = __float2bfloat16(v.y);
        __nv_bfloat16 hz = __float2bfloat16(v.z), hw = __float2bfloat16(v.w);
        __nv_bfloat162 h01; h01.x = hx; h01.y = hy;
        __nv_bfloat162 h23; h23.x = hz; h23.y = hw;
        __nv_bfloat162 l01; l01.x = __float2bfloat16(v.x - __bfloat162float(hx));
                            l01.y = __float2bfloat16(v.y - __bfloat162float(hy));
        __nv_bfloat162 l23; l23.x = __float2bfloat16(v.z - __bfloat162float(hz));
                            l23.y = __float2bfloat16(v.w - __bfloat162float(hw));
        *(__nv_bfloat162*)(g_hi + base)     = h01;
        *(__nv_bfloat162*)(g_hi + base + 2) = h23;
        *(__nv_bfloat162*)(g_lo + base)     = l01;
        *(__nv_bfloat162*)(g_lo + base + 2) = l23;
    }
    if (lane == 0) {
        float pos = cx * inv1 * inv2;
        g_pos[gw] = pos;            g_pos[gw + NB] = pos;
        g_self[gw] = ss1 * inv1 * inv1;
        g_self[gw + NB] = ss2 * inv2 * inv2;
        g_rowsum[gw] = 0.0f;        g_rowsum[gw + NB] = 0.0f;
    }
}

// ---------------- K2: HMMA sim-GEMM (upper triangle) + exp + row/col sums ----------------
extern __shared__ char smem_raw[];

__global__ void __launch_bounds__(256, 2) k_gemm() {
    const int tid  = threadIdx.x;
    const int wid  = tid >> 5;
    const int lane = tid & 31;

    // decode upper-triangle tile (bi <= bj) from linear blockIdx
    int t = blockIdx.x;
    int bi = (int)(64.5f - sqrtf(64.5f * 64.5f - 2.0f * (float)t));
    while (bi * NTILE - (bi * (bi - 1)) / 2 > t) --bi;
    while ((bi + 1) * NTILE - ((bi + 1) * bi) / 2 <= t) ++bi;
    const int bj = bi + (t - (bi * NTILE - (bi * (bi - 1)) / 2));
    const bool diag = (bi == bj);
    const int r0 = bi * 128;
    const int c0 = bj * 128;

    float* smrows = (float*)(smem_raw + SM_ROWS);
    float* smcols = (float*)(smem_raw + SM_COLS);
    if (tid < 128) { smrows[tid] = 0.0f; smcols[tid] = 0.0f; }

    // load A_hi / A_lo (rows r0..+127) and B_hi (rows c0..+127)
#pragma unroll
    for (int it = 0; it < 8; ++it) {
        int idx = tid + it * 256;
        int row = idx >> 4;
        int seg = idx & 15;
        uint32_t so = (uint32_t)(row * PITCH + seg * 16);
        *(uint4*)(smem_raw + SM_AHI + so) =
            *(const uint4*)(g_hi + (size_t)(r0 + row) * DDIM + seg * 8);
        *(uint4*)(smem_raw + SM_ALO + so) =
            *(const uint4*)(g_lo + (size_t)(r0 + row) * DDIM + seg * 8);
        *(uint4*)(smem_raw + SM_B + so) =
            *(const uint4*)(g_hi + (size_t)(c0 + row) * DDIM + seg * 8);
    }
    __syncthreads();

    const uint32_t sb = smem_u32(smem_raw);
    const int wm = wid >> 2;          // 0..1 -> rows 64*wm
    const int wn = wid & 3;           // 0..3 -> cols 32*wn

    const uint32_t a_base = sb +
        (uint32_t)((64 * wm + (lane & 15)) * PITCH + (lane >> 4) * 16);
    const int brow = 32 * wn + (lane & 7) + ((lane >> 4) << 3);
    const uint32_t b_base = sb + SM_B +
        (uint32_t)(brow * PITCH + ((lane >> 3) & 1) * 16);

    float acc[4][4][4];
#pragma unroll
    for (int mi = 0; mi < 4; ++mi)
#pragma unroll
        for (int nj = 0; nj < 4; ++nj)
#pragma unroll
            for (int e = 0; e < 4; ++e) acc[mi][nj][e] = 0.0f;

#pragma unroll
    for (int kk = 0; kk < 8; ++kk) {
        uint32_t b[2][4];
        ldsm4(b[0], b_base + kk * 32);
        ldsm4(b[1], b_base + 16 * PITCH + kk * 32);
#pragma unroll
        for (int g = 0; g < 2; ++g) {
            uint32_t ab = a_base + (g ? SM_ALO : SM_AHI) + kk * 32;
#pragma unroll
            for (int mi = 0; mi < 4; ++mi) {
                uint32_t a[4];
                ldsm4(a, ab + mi * 16 * PITCH);
                mma16816(acc[mi][0], a, b[0][0], b[0][1]);
                mma16816(acc[mi][1], a, b[0][2], b[0][3]);
                mma16816(acc[mi][2], a, b[1][0], b[1][1]);
                mma16816(acc[mi][3], a, b[1][2], b[1][3]);
            }
        }
    }

    // exp(2*sim) in place
#pragma unroll
    for (int mi = 0; mi < 4; ++mi)
#pragma unroll
        for (int nj = 0; nj < 4; ++nj)
#pragma unroll
            for (int e = 0; e < 4; ++e)
                acc[mi][nj][e] = __expf(2.0f * acc[mi][nj][e]);

    // row partial sums
    const int rbase = 64 * wm + (lane >> 2);
#pragma unroll
    for (int mi = 0; mi < 4; ++mi) {
        float slo = 0.0f, shi = 0.0f;
#pragma unroll
        for (int nj = 0; nj < 4; ++nj) {
            slo += acc[mi][nj][0] + acc[mi][nj][1];
            shi += acc[mi][nj][2] + acc[mi][nj][3];
        }
        atomicAdd(&smrows[rbase + 16 * mi],     slo);
        atomicAdd(&smrows[rbase + 16 * mi + 8], shi);
    }

    // column partial sums (off-diagonal tiles credit the transpose rows)
    if (!diag) {
#pragma unroll
        for (int nj = 0; nj < 4; ++nj) {
#pragma unroll
            for (int c2 = 0; c2 < 2; ++c2) {
                float v = 0.0f;
#pragma unroll
                for (int mi = 0; mi < 4; ++mi)
                    v += acc[mi][nj][c2] + acc[mi][nj][c2 + 2];
                v += __shfl_down_sync(0xffffffffu, v, 16);
                v += __shfl_down_sync(0xffffffffu, v, 8);
                v += __shfl_down_sync(0xffffffffu, v, 4);
                if (lane < 4)
                    atomicAdd(&smcols[32 * wn + nj * 8 + lane * 2 + c2], v);
            }
        }
    }
    __syncthreads();
    if (tid < 128) {
        atomicAdd(&g_rowsum[r0 + tid], smrows[tid]);
        if (!diag) atomicAdd(&g_rowsum[c0 + tid], smcols[tid]);
    }
}

// ---------------- K3: final reduction ----------------
__global__ void __launch_bounds__(256) k_final(float* __restrict__ out) {
    __shared__ float red[256];
    int tid = threadIdx.x;
    float local = 0.0f;
    for (int r = tid; r < NROWS; r += 256) {
        float den = g_rowsum[r] - __expf(2.0f * g_self[r]);
        local += __logf(den) - 2.0f * g_pos[r];
    }
    red[tid] = local;
    __syncthreads();
#pragma unroll
    for (int o = 128; o; o >>= 1) {
        if (tid < o) red[tid] += red[tid + o];
        __syncthreads();
    }
    if (tid == 0) out[0] = red[0] / (float)NROWS;
}

// ---------------- launcher ----------------
extern "C" void kernel_launch(void* const* d_in, const int* in_sizes, int n_in,
                              void* d_out, int out_size) {
    const float* p1 = (const float*)d_in[0];
    const float* p2 = (const float*)d_in[1];
    float* out = (float*)d_out;

    cudaFuncSetAttribute(k_gemm, cudaFuncAttributeMaxDynamicSharedMemorySize, SMEM_SZ);

    k_norm<<<NB / 8, 256>>>(p1, p2);
    k_gemm<<<NCTA, 256, SMEM_SZ>>>();
    k_final<<<1, 256>>>(out);
}

// round 5
// speedup vs baseline: 6.5833x; 1.6774x over previous
#include <cuda_runtime.h>
#include <cuda_bf16.h>
#include <math.h>
#include <stdint.h>

#define NB     4096
#define NROWS  8192
#define DDIM   128
#define NTILE  64          // 8192 / 128
#define NCTA   2080        // NTILE*(NTILE+1)/2 upper-triangle tiles

// ---------------- static scratch (no allocations allowed) ----------------
__device__ __nv_bfloat16 g_hi[NROWS * DDIM];
__device__ float         g_rowsum[NROWS];
__device__ float         g_pos[NROWS];
__device__ float         g_self[NROWS];

// ---------------- helpers ----------------
__device__ __forceinline__ uint32_t smem_u32(const void* p) {
    uint32_t a;
    asm("{ .reg .u64 t; cvta.to.shared.u64 t, %1; cvt.u32.u64 %0, t; }"
        : "=r"(a) : "l"(p));
    return a;
}
__device__ __forceinline__ void ldsm4(uint32_t* r, uint32_t addr) {
    asm volatile("ldmatrix.sync.aligned.m8n8.x4.shared.b16 {%0,%1,%2,%3}, [%4];"
                 : "=r"(r[0]), "=r"(r[1]), "=r"(r[2]), "=r"(r[3]) : "r"(addr));
}
__device__ __forceinline__ void mma16816(float* d, const uint32_t* a,
                                         uint32_t b0, uint32_t b1) {
    asm volatile("mma.sync.aligned.m16n8k16.row.col.f32.bf16.bf16.f32 "
                 "{%0,%1,%2,%3}, {%4,%5,%6,%7}, {%8,%9}, {%0,%1,%2,%3};"
                 : "+f"(d[0]), "+f"(d[1]), "+f"(d[2]), "+f"(d[3])
                 : "r"(a[0]), "r"(a[1]), "r"(a[2]), "r"(a[3]), "r"(b0), "r"(b1));
}

// smem tile layout: 128 rows, pitch 272 B (17x16B -> conflict-free ldmatrix)
#define PITCH    272
#define SM_A     0
#define SM_B     (128 * PITCH)
#define SM_ROWS  (2 * 128 * PITCH)
#define SM_COLS  (SM_ROWS + 128 * 4)
#define SMEM_SZ  (SM_COLS + 128 * 4)

// ---------------- K1: normalize pair + bf16 + positives/self ----------------
__global__ void __launch_bounds__(256) k_norm(const float* __restrict__ p1,
                                              const float* __restrict__ p2) {
    int gw = (blockIdx.x * blockDim.x + threadIdx.x) >> 5;   // pair index 0..NB-1
    int lane = threadIdx.x & 31;
    if (gw >= NB) return;
    float4 v1 = *(const float4*)(p1 + (size_t)gw * DDIM + lane * 4);
    float4 v2 = *(const float4*)(p2 + (size_t)gw * DDIM + lane * 4);
    float ss1 = v1.x * v1.x + v1.y * v1.y + v1.z * v1.z + v1.w * v1.w;
    float ss2 = v2.x * v2.x + v2.y * v2.y + v2.z * v2.z + v2.w * v2.w;
    float cx  = v1.x * v2.x + v1.y * v2.y + v1.z * v2.z + v1.w * v2.w;
#pragma unroll
    for (int o = 16; o; o >>= 1) {
        ss1 += __shfl_xor_sync(0xffffffffu, ss1, o);
        ss2 += __shfl_xor_sync(0xffffffffu, ss2, o);
        cx  += __shfl_xor_sync(0xffffffffu, cx,  o);
    }
    float inv1 = 1.0f / fmaxf(sqrtf(ss1), 1e-12f);
    float inv2 = 1.0f / fmaxf(sqrtf(ss2), 1e-12f);

#pragma unroll
    for (int half = 0; half < 2; ++half) {
        float4 v = half ? v2 : v1;
        float inv = half ? inv2 : inv1;
        size_t base = (size_t)(half ? gw + NB : gw) * DDIM + lane * 4;
        v.x *= inv; v.y *= inv; v.z *= inv; v.w *= inv;
        __nv_bfloat162 h01; h01.x = __float2bfloat16(v.x); h01.y = __float2bfloat16(v.y);
        __nv_bfloat162 h23; h23.x = __float2bfloat16(v.z); h23.y = __float2bfloat16(v.w);
        *(__nv_bfloat162*)(g_hi + base)     = h01;
        *(__nv_bfloat162*)(g_hi + base + 2) = h23;
    }
    if (lane == 0) {
        float pos = cx * inv1 * inv2;
        g_pos[gw] = pos;            g_pos[gw + NB] = pos;
        g_self[gw] = ss1 * inv1 * inv1;
        g_self[gw + NB] = ss2 * inv2 * inv2;
        g_rowsum[gw] = 0.0f;        g_rowsum[gw + NB] = 0.0f;
    }
}

// ---------------- K2: HMMA sim-GEMM (upper triangle) + exp + row/col sums ----------------
extern __shared__ char smem_raw[];

__global__ void __launch_bounds__(256, 2) k_gemm() {
    const int tid  = threadIdx.x;
    const int wid  = tid >> 5;
    const int lane = tid & 31;

    // decode upper-triangle tile (bi <= bj) from linear blockIdx
    int t = blockIdx.x;
    int bi = (int)(64.5f - sqrtf(64.5f * 64.5f - 2.0f * (float)t));
    while (bi * NTILE - (bi * (bi - 1)) / 2 > t) --bi;
    while ((bi + 1) * NTILE - ((bi + 1) * bi) / 2 <= t) ++bi;
    const int bj = bi + (t - (bi * NTILE - (bi * (bi - 1)) / 2));
    const bool diag = (bi == bj);
    const int r0 = bi * 128;
    const int c0 = bj * 128;

    float* smrows = (float*)(smem_raw + SM_ROWS);
    float* smcols = (float*)(smem_raw + SM_COLS);
    if (tid < 128) { smrows[tid] = 0.0f; smcols[tid] = 0.0f; }

    // load A (rows r0..+127) and B (rows c0..+127)
#pragma unroll
    for (int it = 0; it < 8; ++it) {
        int idx = tid + it * 256;
        int row = idx >> 4;
        int seg = idx & 15;
        uint32_t so = (uint32_t)(row * PITCH + seg * 16);
        *(uint4*)(smem_raw + SM_A + so) =
            *(const uint4*)(g_hi + (size_t)(r0 + row) * DDIM + seg * 8);
        *(uint4*)(smem_raw + SM_B + so) =
            *(const uint4*)(g_hi + (size_t)(c0 + row) * DDIM + seg * 8);
    }
    __syncthreads();

    const uint32_t sb = smem_u32(smem_raw);
    const int wm = wid >> 2;          // 0..1 -> rows 64*wm
    const int wn = wid & 3;           // 0..3 -> cols 32*wn

    const uint32_t a_base = sb +
        (uint32_t)((64 * wm + (lane & 15)) * PITCH + (lane >> 4) * 16);
    const int brow = 32 * wn + (lane & 7) + ((lane >> 4) << 3);
    const uint32_t b_base = sb + SM_B +
        (uint32_t)(brow * PITCH + ((lane >> 3) & 1) * 16);

    float acc[4][4][4];
#pragma unroll
    for (int mi = 0; mi < 4; ++mi)
#pragma unroll
        for (int nj = 0; nj < 4; ++nj)
#pragma unroll
            for (int e = 0; e < 4; ++e) acc[mi][nj][e] = 0.0f;

#pragma unroll
    for (int kk = 0; kk < 8; ++kk) {
        uint32_t b[2][4];
        ldsm4(b[0], b_base + kk * 32);
        ldsm4(b[1], b_base + 16 * PITCH + kk * 32);
#pragma unroll
        for (int mi = 0; mi < 4; ++mi) {
            uint32_t a[4];
            ldsm4(a, a_base + kk * 32 + mi * 16 * PITCH);
            mma16816(acc[mi][0], a, b[0][0], b[0][1]);
            mma16816(acc[mi][1], a, b[0][2], b[0][3]);
            mma16816(acc[mi][2], a, b[1][0], b[1][1]);
            mma16816(acc[mi][3], a, b[1][2], b[1][3]);
        }
    }

    // exp(2*sim) in place
#pragma unroll
    for (int mi = 0; mi < 4; ++mi)
#pragma unroll
        for (int nj = 0; nj < 4; ++nj)
#pragma unroll
            for (int e = 0; e < 4; ++e)
                acc[mi][nj][e] = __expf(2.0f * acc[mi][nj][e]);

    // row partial sums: quad shfl-reduce, then 1 atomic per row per quad
    const int rbase = 64 * wm + (lane >> 2);
#pragma unroll
    for (int mi = 0; mi < 4; ++mi) {
        float slo = 0.0f, shi = 0.0f;
#pragma unroll
        for (int nj = 0; nj < 4; ++nj) {
            slo += acc[mi][nj][0] + acc[mi][nj][1];
            shi += acc[mi][nj][2] + acc[mi][nj][3];
        }
        slo += __shfl_xor_sync(0xffffffffu, slo, 1);
        slo += __shfl_xor_sync(0xffffffffu, slo, 2);
        shi += __shfl_xor_sync(0xffffffffu, shi, 1);
        shi += __shfl_xor_sync(0xffffffffu, shi, 2);
        if ((lane & 3) == 0) {
            atomicAdd(&smrows[rbase + 16 * mi],     slo);
            atomicAdd(&smrows[rbase + 16 * mi + 8], shi);
        }
    }

    // column partial sums (off-diagonal tiles credit the transpose rows)
    if (!diag) {
#pragma unroll
        for (int nj = 0; nj < 4; ++nj) {
#pragma unroll
            for (int c2 = 0; c2 < 2; ++c2) {
                float v = 0.0f;
#pragma unroll
                for (int mi = 0; mi < 4; ++mi)
                    v += acc[mi][nj][c2] + acc[mi][nj][c2 + 2];
                v += __shfl_down_sync(0xffffffffu, v, 16);
                v += __shfl_down_sync(0xffffffffu, v, 8);
                v += __shfl_down_sync(0xffffffffu, v, 4);
                if (lane < 4)
                    atomicAdd(&smcols[32 * wn + nj * 8 + lane * 2 + c2], v);
            }
        }
    }
    __syncthreads();
    if (tid < 128) {
        atomicAdd(&g_rowsum[r0 + tid], smrows[tid]);
        if (!diag) atomicAdd(&g_rowsum[c0 + tid], smcols[tid]);
    }
}

// ---------------- K3: final reduction ----------------
__global__ void __launch_bounds__(1024) k_final(float* __restrict__ out) {
    __shared__ float red[1024];
    int tid = threadIdx.x;
    float local = 0.0f;
#pragma unroll
    for (int r = tid; r < NROWS; r += 1024) {
        float den = g_rowsum[r] - __expf(2.0f * g_self[r]);
        local += __logf(den) - 2.0f * g_pos[r];
    }
    red[tid] = local;
    __syncthreads();
#pragma unroll
    for (int o = 512; o; o >>= 1) {
        if (tid < o) red[tid] += red[tid + o];
        __syncthreads();
    }
    if (tid == 0) out[0] = red[0] / (float)NROWS;
}

// ---------------- launcher ----------------
extern "C" void kernel_launch(void* const* d_in, const int* in_sizes, int n_in,
                              void* d_out, int out_size) {
    const float* p1 = (const float*)d_in[0];
    const float* p2 = (const float*)d_in[1];
    float* out = (float*)d_out;

    cudaFuncSetAttribute(k_gemm, cudaFuncAttributeMaxDynamicSharedMemorySize, SMEM_SZ);

    k_norm<<<NB / 8, 256>>>(p1, p2);
    k_gemm<<<NCTA, 256, SMEM_SZ>>>();
    k_final<<<1, 1024>>>(out);
}